// round 13
// baseline (speedup 1.0000x reference)
#include <cuda_runtime.h>
#include <cuda_fp16.h>
#include <math.h>
#include <cstdint>

// Problem constants
#define BB 4
#define NN 16384
#define CC 128
#define NP 1024          // (128/4)^2 KV tokens per batch
#define DH 64
#define LN_EPS 1e-6f
#define QSCALE_LOG2 0.1803368801111601f   // 0.125 * log2(e)

typedef unsigned int uint32;

// ---- scratch (device globals; no allocation allowed) ----
__device__ __half g_aoh[(size_t)BB * NN * CC];   // attn out half
__device__ __half g_kh [BB * NP * CC];           // K half
__device__ __half g_vh [BB * NP * CC];           // V half
__device__ float  g_cpart[4 * BB * NP * CC];     // conv split-K partials
__device__ __half g_wqT[CC * CC];                // W^T half, [n][k]
__device__ __half g_wkT[CC * CC];
__device__ __half g_wvT[CC * CC];
__device__ __half g_wpT[CC * CC];
__device__ __half g_wcT[CC * 2048];              // conv weight^T [cout][2048]

// ---- fp16 k16 mma (f32 accum) ----
__device__ __forceinline__ void mma_f16(
    float& c0, float& c1, float& c2, float& c3,
    uint32 a0, uint32 a1, uint32 a2, uint32 a3,
    uint32 b0, uint32 b1)
{
    asm volatile(
        "mma.sync.aligned.m16n8k16.row.col.f32.f16.f16.f32 "
        "{%0,%1,%2,%3}, {%4,%5,%6,%7}, {%8,%9}, {%0,%1,%2,%3};\n"
        : "+f"(c0), "+f"(c1), "+f"(c2), "+f"(c3)
        : "r"(a0), "r"(a1), "r"(a2), "r"(a3), "r"(b0), "r"(b1));
}
// fp16 k16 mma with fp16 accumulators (2 regs = 4 halves)
__device__ __forceinline__ void mma_f16h(
    uint32& d0, uint32& d1,
    uint32 a0, uint32 a1, uint32 a2, uint32 a3,
    uint32 b0, uint32 b1)
{
    asm volatile(
        "mma.sync.aligned.m16n8k16.row.col.f16.f16.f16.f16 "
        "{%0,%1}, {%2,%3,%4,%5}, {%6,%7}, {%0,%1};\n"
        : "+r"(d0), "+r"(d1)
        : "r"(a0), "r"(a1), "r"(a2), "r"(a3), "r"(b0), "r"(b1));
}
__device__ __forceinline__ void ldsm4(
    uint32& d0, uint32& d1, uint32& d2, uint32& d3, uint32 addr)
{
    asm volatile("ldmatrix.sync.aligned.m8n8.x4.shared.b16 {%0,%1,%2,%3}, [%4];"
                 : "=r"(d0), "=r"(d1), "=r"(d2), "=r"(d3) : "r"(addr));
}
__device__ __forceinline__ void ldsm4t(
    uint32& d0, uint32& d1, uint32& d2, uint32& d3, uint32 addr)
{
    asm volatile("ldmatrix.sync.aligned.m8n8.x4.trans.shared.b16 {%0,%1,%2,%3}, [%4];"
                 : "=r"(d0), "=r"(d1), "=r"(d2), "=r"(d3) : "r"(addr));
}
__device__ __forceinline__ uint32 smem_u32(const void* p) {
    uint32 a;
    asm("{ .reg .u64 t; cvta.to.shared.u64 t, %1; cvt.u32.u64 %0, t; }"
        : "=r"(a) : "l"(p));
    return a;
}
__device__ __forceinline__ void cp16(uint32 dst, const void* src) {
    asm volatile("cp.async.ca.shared.global [%0], [%1], 16;"
                 :: "r"(dst), "l"(src));
}
#define CP_COMMIT() asm volatile("cp.async.commit_group;" ::: "memory")
#define CP_WAIT0()  asm volatile("cp.async.wait_group 0;" ::: "memory")
#define CP_WAIT1()  asm volatile("cp.async.wait_group 1;" ::: "memory")

// 2^x elementwise on a half2 reg; accumulates the (quantized) pair sum
__device__ __forceinline__ uint32 ex2acc(uint32 u, float& acc) {
    uint32 e;
    asm("ex2.approx.f16x2 %0, %1;" : "=r"(e) : "r"(u));
    __half2 eh = *reinterpret_cast<__half2*>(&e);
    float2 f = __half22float2(eh);
    acc += f.x + f.y;
    return e;
}
__device__ __forceinline__ uint4 pack8(float4 f0, float4 f1) {
    __half2 h[4] = {__floats2half2_rn(f0.x, f0.y), __floats2half2_rn(f0.z, f0.w),
                    __floats2half2_rn(f1.x, f1.y), __floats2half2_rn(f1.z, f1.w)};
    return *reinterpret_cast<uint4*>(h);
}
__device__ __forceinline__ uint32 packh2(float a, float b) {
    __half2 h = __floats2half2_rn(a, b);
    return *reinterpret_cast<uint32*>(&h);
}

// ============================================================================
// prep: weight conversions/transposes (tiny)
// ============================================================================
__global__ __launch_bounds__(256) void prep_w(
    const float* __restrict__ Wq, const float* __restrict__ Wk,
    const float* __restrict__ Wv, const float* __restrict__ Wp,
    const float* __restrict__ srk)
{
    const int i = blockIdx.x * 256 + threadIdx.x;
    if (i < 128 * 2048) {
        const int n = i >> 11, k = i & 2047;
        g_wcT[i] = __float2half(srk[k * 128 + n]);
    } else {
        const int j = i - 128 * 2048;
        if (j < 16384) {
            const int n = j >> 7, k = j & 127;
            const int s = k * 128 + n;
            g_wqT[j] = __float2half(Wq[s]);
            g_wkT[j] = __float2half(Wk[s]);
            g_wvT[j] = __float2half(Wv[s]);
            g_wpT[j] = __float2half(Wp[s]);
        }
    }
}

// ============================================================================
// conv: patch GEMM M=4096,K=2048,N=128, split-K x4, pipelined (R9-proven).
// ============================================================================
#define CONVBUF 18432   // 128*72 halves = bytes per buffer

__global__ __launch_bounds__(256) void conv_h(const float* __restrict__ x)
{
    extern __shared__ __align__(16) __half cs[];
    __half* sA = cs;
    __half* sB = cs + 2 * (128 * 72);
    const int tid = threadIdx.x, lane = tid & 31, wid = tid >> 5;
    const int g = lane >> 2, tig = lane & 3;
    const int laneJ = lane >> 3, laneR = lane & 7;
    const int rowBase = blockIdx.x * 128;
    const int wr = (wid & 3) * 32;
    const int wc = (wid >> 2) * 64;
    float* outp = g_cpart + (size_t)blockIdx.y * (BB * NP * CC);

    const uint32 sAb = smem_u32(sA), sBb = smem_u32(sB);
    const uint32 aAddr0 = sAb + (uint32)((wr + (laneJ & 1) * 8 + laneR) * 144
                                         + (laneJ >> 1) * 16);
    const uint32 bAddrW = sBb + (uint32)((wc + laneR) * 144 + laneJ * 16);

    const int lr = tid >> 3;
    const int c8 = (tid & 7) * 8;
    size_t tok0[4];
    #pragma unroll
    for (int i = 0; i < 4; i++) {
        const int m = rowBase + lr + i * 32;
        const int b = m >> 10, p = m & 1023;
        const int pi = p >> 5, pj = p & 31;
        tok0[i] = (size_t)b * NN + (size_t)(pi * 4) * 128 + pj * 4;
    }

    const int kk0 = blockIdx.y * 512;

    float acc[2][8][4];
    #pragma unroll
    for (int m = 0; m < 2; m++)
        #pragma unroll
        for (int n = 0; n < 8; n++)
            #pragma unroll
            for (int q = 0; q < 4; q++) acc[m][n][q] = 0.0f;

    float4 ar[4][2];
    {
        const int k0 = kk0;
        const int di = k0 >> 9, dj = (k0 >> 7) & 3, cin0 = k0 & 127;
        const int pix = di * 128 + dj;
        #pragma unroll
        for (int i = 0; i < 4; i++) {
            const float* src = x + (tok0[i] + pix) * 128 + cin0 + c8;
            ar[i][0] = ((const float4*)src)[0];
            ar[i][1] = ((const float4*)src)[1];
            cp16(sBb + (uint32)((lr + i * 32) * 144 + c8 * 2),
                 g_wcT + (size_t)(lr + i * 32) * 2048 + k0 + c8);
        }
        CP_COMMIT();
        #pragma unroll
        for (int i = 0; i < 4; i++)
            *reinterpret_cast<uint4*>(sA + (lr + i * 32) * 72 + c8) =
                pack8(ar[i][0], ar[i][1]);
    }
    CP_WAIT0();
    __syncthreads();

    for (int cc = 0; cc < 8; cc++) {
        const uint32 cur = (uint32)((cc & 1) * CONVBUF);
        if (cc < 7) {
            const int k0 = kk0 + (cc + 1) * 64;
            const int di = k0 >> 9, dj = (k0 >> 7) & 3, cin0 = k0 & 127;
            const int pix = di * 128 + dj;
            const uint32 nb = (uint32)(((cc + 1) & 1) * CONVBUF);
            #pragma unroll
            for (int i = 0; i < 4; i++) {
                const float* src = x + (tok0[i] + pix) * 128 + cin0 + c8;
                ar[i][0] = ((const float4*)src)[0];
                ar[i][1] = ((const float4*)src)[1];
                cp16(sBb + nb + (uint32)((lr + i * 32) * 144 + c8 * 2),
                     g_wcT + (size_t)(lr + i * 32) * 2048 + k0 + c8);
            }
            CP_COMMIT();
        }
        #pragma unroll
        for (int c = 0; c < 2; c++) {
            uint32 a[2][2][4];
            #pragma unroll
            for (int m = 0; m < 2; m++)
                #pragma unroll
                for (int s2 = 0; s2 < 2; s2++)
                    ldsm4(a[m][s2][0], a[m][s2][1], a[m][s2][2], a[m][s2][3],
                          aAddr0 + cur + m * 2304 + (2 * c + s2) * 32);
            #pragma unroll
            for (int n = 0; n < 8; n++) {
                uint32 b0, b1, b2, b3;
                ldsm4(b0, b1, b2, b3, bAddrW + cur + n * 1152 + c * 64);
                #pragma unroll
                for (int m = 0; m < 2; m++) {
                    mma_f16(acc[m][n][0], acc[m][n][1], acc[m][n][2], acc[m][n][3],
                            a[m][0][0], a[m][0][1], a[m][0][2], a[m][0][3], b0, b1);
                    mma_f16(acc[m][n][0], acc[m][n][1], acc[m][n][2], acc[m][n][3],
                            a[m][1][0], a[m][1][1], a[m][1][2], a[m][1][3], b2, b3);
                }
            }
        }
        if (cc < 7) {
            __syncthreads();
            __half* sAn = sA + ((cc + 1) & 1) * (128 * 72);
            #pragma unroll
            for (int i = 0; i < 4; i++)
                *reinterpret_cast<uint4*>(sAn + (lr + i * 32) * 72 + c8) =
                    pack8(ar[i][0], ar[i][1]);
            CP_WAIT0();
            __syncthreads();
        }
    }
    #pragma unroll
    for (int m = 0; m < 2; m++) {
        #pragma unroll
        for (int n = 0; n < 8; n++) {
            const int col = wc + n * 8 + 2 * tig;
            const size_t r0 = (size_t)rowBase + wr + m * 16 + g;
            *(float2*)(&outp[r0 * 128 + col]) =
                make_float2(acc[m][n][0], acc[m][n][1]);
            *(float2*)(&outp[(r0 + 8) * 128 + col]) =
                make_float2(acc[m][n][2], acc[m][n][3]);
        }
    }
}

// ============================================================================
// ln_kv: FUSED reduce split-K partials + bias + LayerNorm + K/V projections.
//   32 CTAs x 256 threads; each CTA owns 128 rows. Wk/Wv prefetched via
//   cp.async while LN math runs; LN result goes straight to the smem A tile
//   (no global xr roundtrip); then the proven mma body runs twice.
//   smem: sA 128x136h (34816) + sBk (34816) + sBv (34816) = 104448 B.
// ============================================================================
#define LNKV_SMEM (3 * 128 * 136 * 2)   // 104448

__global__ __launch_bounds__(256) void ln_kv(
    const float* __restrict__ bias,
    const float* __restrict__ gamma, const float* __restrict__ beta)
{
    extern __shared__ __align__(16) __half ls[];
    __half* sA  = ls;                    // 128 x 136
    __half* sBk = ls + 128 * 136;        // 128 x 136
    __half* sBv = ls + 2 * 128 * 136;    // 128 x 136
    const int tid = threadIdx.x, lane = tid & 31, wid = tid >> 5;
    const int g = lane >> 2, tig = lane & 3;
    const int laneJ = lane >> 3, laneR = lane & 7;
    const size_t rowBase = (size_t)blockIdx.x * 128;

    const uint32 sAb = smem_u32(sA);
    const uint32 sBkb = smem_u32(sBk), sBvb = smem_u32(sBv);

    // prefetch Wk, Wv (each: 128 rows x 256 B; 8 cp16/thread/weight)
    {
        const int row = tid >> 1;             // 0..127
        const int part = tid & 1;             // half-row
        const uint32 doff = (uint32)(row * 272 + part * 128);
        const __half* wk = g_wkT + (size_t)row * 128 + part * 64;
        const __half* wv = g_wvT + (size_t)row * 128 + part * 64;
        #pragma unroll
        for (int j = 0; j < 8; j++) {
            cp16(sBkb + doff + j * 16, wk + j * 8);
            cp16(sBvb + doff + j * 16, wv + j * 8);
        }
        CP_COMMIT();
    }

    // LN: thread owns half a row (64 values) in registers
    const int row = tid >> 1;
    const int col0 = (tid & 1) * 64;
    const size_t o = (rowBase + row) * 128 + col0;
    const size_t STRIDE = (size_t)BB * NP * CC;

    float4 v[16];
    float s = 0.0f, s2 = 0.0f;
    #pragma unroll
    for (int j = 0; j < 16; j++) {
        float4 a0 = ((const float4*)(g_cpart + o))[j];
        float4 a1 = ((const float4*)(g_cpart + STRIDE + o))[j];
        float4 a2 = ((const float4*)(g_cpart + 2 * STRIDE + o))[j];
        float4 a3 = ((const float4*)(g_cpart + 3 * STRIDE + o))[j];
        float4 bb = ((const float4*)(bias + col0))[j];
        float4 r;
        r.x = a0.x + a1.x + a2.x + a3.x + bb.x;
        r.y = a0.y + a1.y + a2.y + a3.y + bb.y;
        r.z = a0.z + a1.z + a2.z + a3.z + bb.z;
        r.w = a0.w + a1.w + a2.w + a3.w + bb.w;
        v[j] = r;
        s  += r.x + r.y + r.z + r.w;
        s2 += r.x * r.x + r.y * r.y + r.z * r.z + r.w * r.w;
    }
    // combine the two half-row threads (adjacent lanes)
    s  += __shfl_xor_sync(0xffffffffu, s,  1);
    s2 += __shfl_xor_sync(0xffffffffu, s2, 1);
    const float mu  = s * (1.0f / 128.0f);
    const float var = s2 * (1.0f / 128.0f) - mu * mu;
    const float rstd = rsqrtf(var + LN_EPS);

    #pragma unroll
    for (int j = 0; j < 8; j++) {
        float4 ga0 = ((const float4*)(gamma + col0))[2 * j];
        float4 ga1 = ((const float4*)(gamma + col0))[2 * j + 1];
        float4 be0 = ((const float4*)(beta + col0))[2 * j];
        float4 be1 = ((const float4*)(beta + col0))[2 * j + 1];
        float4 r0 = v[2 * j], r1 = v[2 * j + 1];
        r0.x = (r0.x - mu) * rstd * ga0.x + be0.x;
        r0.y = (r0.y - mu) * rstd * ga0.y + be0.y;
        r0.z = (r0.z - mu) * rstd * ga0.z + be0.z;
        r0.w = (r0.w - mu) * rstd * ga0.w + be0.w;
        r1.x = (r1.x - mu) * rstd * ga1.x + be1.x;
        r1.y = (r1.y - mu) * rstd * ga1.y + be1.y;
        r1.z = (r1.z - mu) * rstd * ga1.z + be1.z;
        r1.w = (r1.w - mu) * rstd * ga1.w + be1.w;
        *reinterpret_cast<uint4*>(sA + row * 136 + col0 + j * 8) = pack8(r0, r1);
    }
    CP_WAIT0();
    __syncthreads();

    // GEMM phase: fragment addresses (proven layout, stride 272 B)
    const int wr = (wid & 3) * 32;
    const int wc = (wid >> 2) * 64;
    const uint32 aAddr0 = sAb + (uint32)((wr + (laneJ & 1) * 8 + laneR) * 272
                                         + (laneJ >> 1) * 16);

    // A fragments are shared by both gemms: load once
    uint32 afr[4][2][4];
    #pragma unroll
    for (int c = 0; c < 4; c++)
        #pragma unroll
        for (int s2i = 0; s2i < 2; s2i++) {
            #pragma unroll
            for (int m = 0; m < 2; m++) { (void)m; }
        }
    #pragma unroll
    for (int c = 0; c < 4; c++) {
        #pragma unroll
        for (int s2i = 0; s2i < 2; s2i++) {
            // pack [m][...]: we reload per m below to save regs; instead store both m
        }
    }

    #pragma unroll
    for (int wsel = 0; wsel < 2; wsel++) {
        const uint32 bAddrW = (wsel ? sBvb : sBkb)
                            + (uint32)((wc + laneR) * 272 + laneJ * 16);
        __half* outv = wsel ? g_vh : g_kh;

        float acc[2][8][4];
        #pragma unroll
        for (int m = 0; m < 2; m++)
            #pragma unroll
            for (int n = 0; n < 8; n++)
                #pragma unroll
                for (int q = 0; q < 4; q++) acc[m][n][q] = 0.0f;

        #pragma unroll
        for (int c = 0; c < 4; c++) {
            uint32 a[2][2][4];
            #pragma unroll
            for (int m = 0; m < 2; m++)
                #pragma unroll
                for (int s2i = 0; s2i < 2; s2i++)
                    ldsm4(a[m][s2i][0], a[m][s2i][1], a[m][s2i][2], a[m][s2i][3],
                          aAddr0 + m * 4352 + (2 * c + s2i) * 32);
            #pragma unroll
            for (int n = 0; n < 8; n++) {
                uint32 b0, b1, b2, b3;
                ldsm4(b0, b1, b2, b3, bAddrW + n * 2176 + c * 64);
                #pragma unroll
                for (int m = 0; m < 2; m++) {
                    mma_f16(acc[m][n][0], acc[m][n][1], acc[m][n][2], acc[m][n][3],
                            a[m][0][0], a[m][0][1], a[m][0][2], a[m][0][3], b0, b1);
                    mma_f16(acc[m][n][0], acc[m][n][1], acc[m][n][2], acc[m][n][3],
                            a[m][1][0], a[m][1][1], a[m][1][2], a[m][1][3], b2, b3);
                }
            }
        }
        #pragma unroll
        for (int m = 0; m < 2; m++) {
            #pragma unroll
            for (int n = 0; n < 8; n++) {
                const int col = wc + n * 8 + 2 * tig;
                const size_t r0 = rowBase + wr + m * 16 + g;
                __half2* op = reinterpret_cast<__half2*>(outv);
                op[(r0 * 128 + col) >> 1] =
                    __floats2half2_rn(acc[m][n][0], acc[m][n][1]);
                op[((r0 + 8) * 128 + col) >> 1] =
                    __floats2half2_rn(acc[m][n][2], acc[m][n][3]);
            }
        }
    }
}

// ============================================================================
// gemm (single-phase) for the output projection (R12-proven)
// ============================================================================
#define GEMM_SMEM (2 * 128 * 136 * 2)   // 69632 bytes

__global__ __launch_bounds__(256) void gemm_out(float* __restrict__ out)
{
    extern __shared__ __align__(16) __half gs[];
    __half* sA = gs;
    __half* sB = gs + 128 * 136;
    const size_t rowBase = (size_t)blockIdx.x * 128;
    const int tid = threadIdx.x, lane = tid & 31, wid = tid >> 5;
    const int g = lane >> 2, tig = lane & 3;
    const int laneJ = lane >> 3, laneR = lane & 7;
    const int wr = (wid & 3) * 32;
    const int wc = (wid >> 2) * 64;
    const int lr = tid >> 3;
    const int c16 = (tid & 7) * 16;

    const uint32 sAb = smem_u32(sA), sBb = smem_u32(sB);
    const uint32 aAddr0 = sAb + (uint32)((wr + (laneJ & 1) * 8 + laneR) * 272
                                         + (laneJ >> 1) * 16);
    const uint32 bAddrW = sBb + (uint32)((wc + laneR) * 272 + laneJ * 16);

    #pragma unroll
    for (int i = 0; i < 4; i++) {
        const int r = lr + i * 32;
        const __half* Ah = g_aoh + (rowBase + r) * 128 + c16;
        *reinterpret_cast<uint4*>(sA + r * 136 + c16)     = ((const uint4*)Ah)[0];
        *reinterpret_cast<uint4*>(sA + r * 136 + c16 + 8) = ((const uint4*)Ah)[1];
        const __half* Wp = g_wpT + (size_t)r * 128 + c16;
        *reinterpret_cast<uint4*>(sB + r * 136 + c16)     = ((const uint4*)Wp)[0];
        *reinterpret_cast<uint4*>(sB + r * 136 + c16 + 8) = ((const uint4*)Wp)[1];
    }
    __syncthreads();

    float acc[2][8][4];
    #pragma unroll
    for (int m = 0; m < 2; m++)
        #pragma unroll
        for (int n = 0; n < 8; n++)
            #pragma unroll
            for (int q = 0; q < 4; q++) acc[m][n][q] = 0.0f;

    #pragma unroll
    for (int c = 0; c < 4; c++) {
        uint32 a[2][2][4];
        #pragma unroll
        for (int m = 0; m < 2; m++)
            #pragma unroll
            for (int s2 = 0; s2 < 2; s2++)
                ldsm4(a[m][s2][0], a[m][s2][1], a[m][s2][2], a[m][s2][3],
                      aAddr0 + m * 4352 + (2 * c + s2) * 32);
        #pragma unroll
        for (int n = 0; n < 8; n++) {
            uint32 b0, b1, b2, b3;
            ldsm4(b0, b1, b2, b3, bAddrW + n * 2176 + c * 64);
            #pragma unroll
            for (int m = 0; m < 2; m++) {
                mma_f16(acc[m][n][0], acc[m][n][1], acc[m][n][2], acc[m][n][3],
                        a[m][0][0], a[m][0][1], a[m][0][2], a[m][0][3], b0, b1);
                mma_f16(acc[m][n][0], acc[m][n][1], acc[m][n][2], acc[m][n][3],
                        a[m][1][0], a[m][1][1], a[m][1][2], a[m][1][3], b2, b3);
            }
        }
    }
    #pragma unroll
    for (int m = 0; m < 2; m++) {
        #pragma unroll
        for (int n = 0; n < 8; n++) {
            const int col = wc + n * 8 + 2 * tig;
            const size_t r0 = rowBase + wr + m * 16 + g;
            *(float2*)(out + r0 * 128 + col) =
                make_float2(acc[m][n][0], acc[m][n][1]);
            *(float2*)(out + (r0 + 8) * 128 + col) =
                make_float2(acc[m][n][2], acc[m][n][3]);
        }
    }
}

// ============================================================================
// fused flash attention (R12-proven): in-kernel Q projection (head slice),
//   3-stage cp.async KV pipeline (55.3 KB smem, 3 CTAs/SM), f16-accum S +
//   direct ex2, f32-accum PV. CTA = 128 queries x one (b,h), 256 threads.
// ============================================================================
#define STAGEB 18432
#define ATTN_SMEM (3 * STAGEB)   // 55296

__device__ __forceinline__ void kv_prefetch(
    uint32 kDst, uint32 vDst, const __half* Kg, const __half* Vg,
    int chunk, int lr, int c8)
{
    const size_t nb = (size_t)(chunk * 64) * CC;
    cp16(kDst,            Kg + nb + (size_t)lr * CC + c8);
    cp16(kDst + 32 * 144, Kg + nb + (size_t)(lr + 32) * CC + c8);
    cp16(vDst,            Vg + nb + (size_t)lr * CC + c8);
    cp16(vDst + 32 * 144, Vg + nb + (size_t)(lr + 32) * CC + c8);
}

__global__ __launch_bounds__(256, 3) void attn_f(const float* __restrict__ x)
{
    extern __shared__ __align__(16) __half as_[];
    const uint32 smb = smem_u32(as_);
    const int tid = threadIdx.x, lane = tid & 31, wid = tid >> 5;
    const int g = lane >> 2, tig = lane & 3;
    const int laneJ = lane >> 3, laneR = lane & 7;
    const int b = blockIdx.y >> 1, h = blockIdx.y & 1;
    const int qbase = blockIdx.x * 128;
    const int wr = wid * 16;

    const __half* Kg = g_kh + ((size_t)b * NP) * CC + h * DH;
    const __half* Vg = g_vh + ((size_t)b * NP) * CC + h * DH;

    // ---------------- Phase 1: Q = x @ Wq[:, h*64 .. h*64+63] ----------------
    __half* sX = as_;                 // 128 x 136 (34816 B)
    __half* sW = as_ + 128 * 136;     // 64 x 136 (17408 B)
    {
        const int lr = tid >> 3;
        const int c16 = (tid & 7) * 16;
        #pragma unroll
        for (int i = 0; i < 4; i++) {
            const int r = lr + i * 32;
            const float* src = x + ((size_t)b * NN + qbase + r) * 128 + c16;
            float4 f0 = ((const float4*)src)[0];
            float4 f1 = ((const float4*)src)[1];
            float4 f2 = ((const float4*)src)[2];
            float4 f3 = ((const float4*)src)[3];
            *reinterpret_cast<uint4*>(sX + r * 136 + c16)     = pack8(f0, f1);
            *reinterpret_cast<uint4*>(sX + r * 136 + c16 + 8) = pack8(f2, f3);
        }
        const int row = tid >> 2;             // 0..63
        const int q4 = (tid & 3) * 32;
        const __half* Wp = g_wqT + (size_t)(h * 64 + row) * 128 + q4;
        #pragma unroll
        for (int j = 0; j < 4; j++)
            *reinterpret_cast<uint4*>(sW + row * 136 + q4 + j * 8) =
                ((const uint4*)(Wp + j * 8))[0];
    }
    __syncthreads();

    uint32 qf[4][4];
    {
        const uint32 sXb = smem_u32(sX), sWb = smem_u32(sW);
        const uint32 aAddrQ = sXb + (uint32)((wr + (laneJ & 1) * 8 + laneR) * 272
                                             + (laneJ >> 1) * 16);
        const uint32 bAddrQ = sWb + (uint32)(laneR * 272 + laneJ * 16);
        float qa[8][4];
        #pragma unroll
        for (int n = 0; n < 8; n++)
            #pragma unroll
            for (int q = 0; q < 4; q++) qa[n][q] = 0.0f;
        #pragma unroll
        for (int c = 0; c < 4; c++) {
            uint32 a[2][4];
            #pragma unroll
            for (int s2 = 0; s2 < 2; s2++)
                ldsm4(a[s2][0], a[s2][1], a[s2][2], a[s2][3],
                      aAddrQ + (2 * c + s2) * 32);
            #pragma unroll
            for (int n = 0; n < 8; n++) {
                uint32 b0, b1, b2, b3;
                ldsm4(b0, b1, b2, b3, bAddrQ + n * 2176 + c * 64);
                mma_f16(qa[n][0], qa[n][1], qa[n][2], qa[n][3],
                        a[0][0], a[0][1], a[0][2], a[0][3], b0, b1);
                mma_f16(qa[n][0], qa[n][1], qa[n][2], qa[n][3],
                        a[1][0], a[1][1], a[1][2], a[1][3], b2, b3);
            }
        }
        #pragma unroll
        for (int s = 0; s < 4; s++) {
            qf[s][0] = packh2(qa[2 * s][0] * QSCALE_LOG2,
                              qa[2 * s][1] * QSCALE_LOG2);
            qf[s][1] = packh2(qa[2 * s][2] * QSCALE_LOG2,
                              qa[2 * s][3] * QSCALE_LOG2);
            qf[s][2] = packh2(qa[2 * s + 1][0] * QSCALE_LOG2,
                              qa[2 * s + 1][1] * QSCALE_LOG2);
            qf[s][3] = packh2(qa[2 * s + 1][2] * QSCALE_LOG2,
                              qa[2 * s + 1][3] * QSCALE_LOG2);
        }
    }
    __syncthreads();   // done with sX/sW; smem becomes KV stages

    // ---------------- Phase 2: KV loop, 3-stage pipeline ----------------
    const uint32 kAddr0 = smb + (uint32)(laneR * 144 + laneJ * 16);
    const uint32 vAddr0 = smb + 9216u + (uint32)((laneJ * 8 + laneR) * 144);
    const int lr = tid >> 3;
    const int c8 = (tid & 7) * 8;
    const uint32 kDst = smb + (uint32)(lr * 144 + c8 * 2);
    const uint32 vDst = smb + 9216u + (uint32)(lr * 144 + c8 * 2);

    float O[8][4];
    #pragma unroll
    for (int n = 0; n < 8; n++)
        #pragma unroll
        for (int q = 0; q < 4; q++) O[n][q] = 0.0f;
    float ls0 = 0.0f, ls1 = 0.0f;

    #pragma unroll
    for (int p = 0; p < 2; p++) {
        kv_prefetch(kDst + p * STAGEB, vDst + p * STAGEB, Kg, Vg, p, lr, c8);
        CP_COMMIT();
    }

    int scur = 0;
    int spre = 2;
    for (int kc = 0; kc < 16; kc++) {
        CP_WAIT1();
        __syncthreads();

        {
            const int nx = kc + 2;
            if (nx < 16) {
                const uint32 st = (uint32)(spre * STAGEB);
                kv_prefetch(kDst + st, vDst + st, Kg, Vg, nx, lr, c8);
            }
            CP_COMMIT();
        }

        const uint32 bo = (uint32)(scur * STAGEB);

        // S = Q K^T (log2 domain), fp16 accumulators
        uint32 Sd[8][2];
        #pragma unroll
        for (int n = 0; n < 8; n++) { Sd[n][0] = 0u; Sd[n][1] = 0u; }
        #pragma unroll
        for (int c = 0; c < 2; c++) {
            #pragma unroll
            for (int n = 0; n < 8; n++) {
                uint32 b0, b1, b2, b3;
                ldsm4(b0, b1, b2, b3, kAddr0 + bo + n * 1152 + c * 64);
                mma_f16h(Sd[n][0], Sd[n][1],
                         qf[2 * c][0], qf[2 * c][1], qf[2 * c][2], qf[2 * c][3],
                         b0, b1);
                mma_f16h(Sd[n][0], Sd[n][1],
                         qf[2 * c + 1][0], qf[2 * c + 1][1], qf[2 * c + 1][2],
                         qf[2 * c + 1][3], b2, b3);
            }
        }

        // P = 2^S on half2 fragments; accumulate quantized sums
        uint32 pf[4][4];
        #pragma unroll
        for (int t = 0; t < 4; t++) {
            pf[t][0] = ex2acc(Sd[2 * t][0],     ls0);
            pf[t][1] = ex2acc(Sd[2 * t][1],     ls1);
            pf[t][2] = ex2acc(Sd[2 * t + 1][0], ls0);
            pf[t][3] = ex2acc(Sd[2 * t + 1][1], ls1);
        }

        // O += P V  (V transposed by ldmatrix.trans), f32 accumulators
        #pragma unroll
        for (int c = 0; c < 2; c++) {
            #pragma unroll
            for (int n = 0; n < 8; n++) {
                uint32 b0, b1, b2, b3;
                ldsm4t(b0, b1, b2, b3, vAddr0 + bo + c * 4608 + n * 16);
                mma_f16(O[n][0], O[n][1], O[n][2], O[n][3],
                        pf[2 * c][0], pf[2 * c][1], pf[2 * c][2], pf[2 * c][3], b0, b1);
                mma_f16(O[n][0], O[n][1], O[n][2], O[n][3],
                        pf[2 * c + 1][0], pf[2 * c + 1][1], pf[2 * c + 1][2],
                        pf[2 * c + 1][3], b2, b3);
            }
        }

        scur = (scur == 2) ? 0 : scur + 1;
        spre = (spre == 2) ? 0 : spre + 1;
    }

    // quad-reduce sums, normalize, store half
    ls0 += __shfl_xor_sync(0xffffffffu, ls0, 1);
    ls0 += __shfl_xor_sync(0xffffffffu, ls0, 2);
    ls1 += __shfl_xor_sync(0xffffffffu, ls1, 1);
    ls1 += __shfl_xor_sync(0xffffffffu, ls1, 2);
    const float inv0 = 1.0f / ls0;
    const float inv1 = 1.0f / ls1;

    __half2* ao2 = reinterpret_cast<__half2*>(g_aoh);
    const size_t org  = ((size_t)b * NN + qbase + wr + g) * 64 + h * 32;
    const size_t org8 = org + 8 * 64;
    #pragma unroll
    for (int n = 0; n < 8; n++) {
        ao2[org  + 4 * n + tig] = __floats2half2_rn(O[n][0] * inv0, O[n][1] * inv0);
        ao2[org8 + 4 * n + tig] = __floats2half2_rn(O[n][2] * inv1, O[n][3] * inv1);
    }
}

// ============================================================================
// launch
// ============================================================================
extern "C" void kernel_launch(void* const* d_in, const int* in_sizes, int n_in,
                              void* d_out, int out_size)
{
    const float* x     = (const float*)d_in[0];
    const float* Wq    = (const float*)d_in[1];
    const float* Wk    = (const float*)d_in[2];
    const float* Wv    = (const float*)d_in[3];
    const float* Wproj = (const float*)d_in[4];
    const float* srk   = (const float*)d_in[5];
    const float* srb   = (const float*)d_in[6];
    const float* gamma = (const float*)d_in[7];
    const float* beta  = (const float*)d_in[8];
    float* out = (float*)d_out;

    const int convSmem = 4 * 128 * 72 * 2;    // 73728
    cudaFuncSetAttribute(conv_h,
        cudaFuncAttributeMaxDynamicSharedMemorySize, convSmem);
    cudaFuncSetAttribute(ln_kv,
        cudaFuncAttributeMaxDynamicSharedMemorySize, LNKV_SMEM);
    cudaFuncSetAttribute(gemm_out,
        cudaFuncAttributeMaxDynamicSharedMemorySize, GEMM_SMEM);
    cudaFuncSetAttribute(attn_f,
        cudaFuncAttributeMaxDynamicSharedMemorySize, ATTN_SMEM);

    // 0) weight conversions
    prep_w<<<1088, 256>>>(Wq, Wk, Wv, Wproj, srk);
    // 1) SR conv (patch GEMM), split-K x4, pipelined
    conv_h<<<dim3(32, 4), 256, convSmem>>>(x);
    // 2+3) fused: reduce partials + bias + LN + K/V projections
    ln_kv<<<32, 256, LNKV_SMEM>>>(srb, gamma, beta);
    // 4+5) fused Q projection + attention (3 CTAs/SM) -> g_aoh (half)
    attn_f<<<dim3(NN / 128, BB * 2), 256, ATTN_SMEM>>>(x);
    // 6) output projection -> d_out (f32)
    gemm_out<<<512, 256, GEMM_SMEM>>>(out);
}

// round 15
// speedup vs baseline: 1.1205x; 1.1205x over previous
#include <cuda_runtime.h>
#include <cuda_fp16.h>
#include <math.h>
#include <cstdint>

// Problem constants
#define BB 4
#define NN 16384
#define CC 128
#define NP 1024          // (128/4)^2 KV tokens per batch
#define DH 64
#define LN_EPS 1e-6f
#define QSCALE_LOG2 0.1803368801111601f   // 0.125 * log2(e)

typedef unsigned int uint32;

// ---- scratch (device globals; no allocation allowed) ----
__device__ __half g_aoh[(size_t)BB * NN * CC];   // attn out half
__device__ __half g_xrh[BB * NP * CC];           // conv+LN half
__device__ __half g_kh [BB * NP * CC];           // K half
__device__ __half g_vh [BB * NP * CC];           // V half
__device__ float  g_cpart[4 * BB * NP * CC];     // conv split-K partials
__device__ __half g_wqT[CC * CC];                // W^T half, [n][k]
__device__ __half g_wkT[CC * CC];
__device__ __half g_wvT[CC * CC];
__device__ __half g_wpT[CC * CC];
__device__ __half g_wcT[CC * 2048];              // conv weight^T [cout][2048]

// ---- fp16 k16 mma (f32 accum) ----
__device__ __forceinline__ void mma_f16(
    float& c0, float& c1, float& c2, float& c3,
    uint32 a0, uint32 a1, uint32 a2, uint32 a3,
    uint32 b0, uint32 b1)
{
    asm volatile(
        "mma.sync.aligned.m16n8k16.row.col.f32.f16.f16.f32 "
        "{%0,%1,%2,%3}, {%4,%5,%6,%7}, {%8,%9}, {%0,%1,%2,%3};\n"
        : "+f"(c0), "+f"(c1), "+f"(c2), "+f"(c3)
        : "r"(a0), "r"(a1), "r"(a2), "r"(a3), "r"(b0), "r"(b1));
}
// fp16 k16 mma with fp16 accumulators (2 regs = 4 halves)
__device__ __forceinline__ void mma_f16h(
    uint32& d0, uint32& d1,
    uint32 a0, uint32 a1, uint32 a2, uint32 a3,
    uint32 b0, uint32 b1)
{
    asm volatile(
        "mma.sync.aligned.m16n8k16.row.col.f16.f16.f16.f16 "
        "{%0,%1}, {%2,%3,%4,%5}, {%6,%7}, {%0,%1};\n"
        : "+r"(d0), "+r"(d1)
        : "r"(a0), "r"(a1), "r"(a2), "r"(a3), "r"(b0), "r"(b1));
}
__device__ __forceinline__ void ldsm4(
    uint32& d0, uint32& d1, uint32& d2, uint32& d3, uint32 addr)
{
    asm volatile("ldmatrix.sync.aligned.m8n8.x4.shared.b16 {%0,%1,%2,%3}, [%4];"
                 : "=r"(d0), "=r"(d1), "=r"(d2), "=r"(d3) : "r"(addr));
}
__device__ __forceinline__ void ldsm4t(
    uint32& d0, uint32& d1, uint32& d2, uint32& d3, uint32 addr)
{
    asm volatile("ldmatrix.sync.aligned.m8n8.x4.trans.shared.b16 {%0,%1,%2,%3}, [%4];"
                 : "=r"(d0), "=r"(d1), "=r"(d2), "=r"(d3) : "r"(addr));
}
__device__ __forceinline__ uint32 smem_u32(const void* p) {
    uint32 a;
    asm("{ .reg .u64 t; cvta.to.shared.u64 t, %1; cvt.u32.u64 %0, t; }"
        : "=r"(a) : "l"(p));
    return a;
}
__device__ __forceinline__ void cp16(uint32 dst, const void* src) {
    asm volatile("cp.async.ca.shared.global [%0], [%1], 16;"
                 :: "r"(dst), "l"(src));
}
#define CP_COMMIT() asm volatile("cp.async.commit_group;" ::: "memory")
#define CP_WAIT0()  asm volatile("cp.async.wait_group 0;" ::: "memory")
#define CP_WAIT1()  asm volatile("cp.async.wait_group 1;" ::: "memory")

// 2^x elementwise on a half2 reg; accumulates the (quantized) pair sum
__device__ __forceinline__ uint32 ex2acc(uint32 u, float& acc) {
    uint32 e;
    asm("ex2.approx.f16x2 %0, %1;" : "=r"(e) : "r"(u));
    __half2 eh = *reinterpret_cast<__half2*>(&e);
    float2 f = __half22float2(eh);
    acc += f.x + f.y;
    return e;
}
__device__ __forceinline__ uint4 pack8(float4 f0, float4 f1) {
    __half2 h[4] = {__floats2half2_rn(f0.x, f0.y), __floats2half2_rn(f0.z, f0.w),
                    __floats2half2_rn(f1.x, f1.y), __floats2half2_rn(f1.z, f1.w)};
    return *reinterpret_cast<uint4*>(h);
}
__device__ __forceinline__ uint32 packh2(float a, float b) {
    __half2 h = __floats2half2_rn(a, b);
    return *reinterpret_cast<uint32*>(&h);
}

// ============================================================================
// prep: weight conversions/transposes (tiny)
// ============================================================================
__global__ __launch_bounds__(256) void prep_w(
    const float* __restrict__ Wq, const float* __restrict__ Wk,
    const float* __restrict__ Wv, const float* __restrict__ Wp,
    const float* __restrict__ srk)
{
    const int i = blockIdx.x * 256 + threadIdx.x;
    if (i < 128 * 2048) {
        const int n = i >> 11, k = i & 2047;
        g_wcT[i] = __float2half(srk[k * 128 + n]);
    } else {
        const int j = i - 128 * 2048;
        if (j < 16384) {
            const int n = j >> 7, k = j & 127;
            const int s = k * 128 + n;
            g_wqT[j] = __float2half(Wq[s]);
            g_wkT[j] = __float2half(Wk[s]);
            g_wvT[j] = __float2half(Wv[s]);
            g_wpT[j] = __float2half(Wp[s]);
        }
    }
}

// ============================================================================
// conv: patch GEMM M=4096,K=2048,N=128, split-K x4, pipelined (R12-proven).
// ============================================================================
#define CONVBUF 18432   // 128*72 halves = bytes per buffer

__global__ __launch_bounds__(256) void conv_h(const float* __restrict__ x)
{
    extern __shared__ __align__(16) __half cs[];
    __half* sA = cs;
    __half* sB = cs + 2 * (128 * 72);
    const int tid = threadIdx.x, lane = tid & 31, wid = tid >> 5;
    const int g = lane >> 2, tig = lane & 3;
    const int laneJ = lane >> 3, laneR = lane & 7;
    const int rowBase = blockIdx.x * 128;
    const int wr = (wid & 3) * 32;
    const int wc = (wid >> 2) * 64;
    float* outp = g_cpart + (size_t)blockIdx.y * (BB * NP * CC);

    const uint32 sAb = smem_u32(sA), sBb = smem_u32(sB);
    const uint32 aAddr0 = sAb + (uint32)((wr + (laneJ & 1) * 8 + laneR) * 144
                                         + (laneJ >> 1) * 16);
    const uint32 bAddrW = sBb + (uint32)((wc + laneR) * 144 + laneJ * 16);

    const int lr = tid >> 3;
    const int c8 = (tid & 7) * 8;
    size_t tok0[4];
    #pragma unroll
    for (int i = 0; i < 4; i++) {
        const int m = rowBase + lr + i * 32;
        const int b = m >> 10, p = m & 1023;
        const int pi = p >> 5, pj = p & 31;
        tok0[i] = (size_t)b * NN + (size_t)(pi * 4) * 128 + pj * 4;
    }

    const int kk0 = blockIdx.y * 512;

    float acc[2][8][4];
    #pragma unroll
    for (int m = 0; m < 2; m++)
        #pragma unroll
        for (int n = 0; n < 8; n++)
            #pragma unroll
            for (int q = 0; q < 4; q++) acc[m][n][q] = 0.0f;

    float4 ar[4][2];
    {
        const int k0 = kk0;
        const int di = k0 >> 9, dj = (k0 >> 7) & 3, cin0 = k0 & 127;
        const int pix = di * 128 + dj;
        #pragma unroll
        for (int i = 0; i < 4; i++) {
            const float* src = x + (tok0[i] + pix) * 128 + cin0 + c8;
            ar[i][0] = ((const float4*)src)[0];
            ar[i][1] = ((const float4*)src)[1];
            cp16(sBb + (uint32)((lr + i * 32) * 144 + c8 * 2),
                 g_wcT + (size_t)(lr + i * 32) * 2048 + k0 + c8);
        }
        CP_COMMIT();
        #pragma unroll
        for (int i = 0; i < 4; i++)
            *reinterpret_cast<uint4*>(sA + (lr + i * 32) * 72 + c8) =
                pack8(ar[i][0], ar[i][1]);
    }
    CP_WAIT0();
    __syncthreads();

    for (int cc = 0; cc < 8; cc++) {
        const uint32 cur = (uint32)((cc & 1) * CONVBUF);
        if (cc < 7) {
            const int k0 = kk0 + (cc + 1) * 64;
            const int di = k0 >> 9, dj = (k0 >> 7) & 3, cin0 = k0 & 127;
            const int pix = di * 128 + dj;
            const uint32 nb = (uint32)(((cc + 1) & 1) * CONVBUF);
            #pragma unroll
            for (int i = 0; i < 4; i++) {
                const float* src = x + (tok0[i] + pix) * 128 + cin0 + c8;
                ar[i][0] = ((const float4*)src)[0];
                ar[i][1] = ((const float4*)src)[1];
                cp16(sBb + nb + (uint32)((lr + i * 32) * 144 + c8 * 2),
                     g_wcT + (size_t)(lr + i * 32) * 2048 + k0 + c8);
            }
            CP_COMMIT();
        }
        #pragma unroll
        for (int c = 0; c < 2; c++) {
            uint32 a[2][2][4];
            #pragma unroll
            for (int m = 0; m < 2; m++)
                #pragma unroll
                for (int s2 = 0; s2 < 2; s2++)
                    ldsm4(a[m][s2][0], a[m][s2][1], a[m][s2][2], a[m][s2][3],
                          aAddr0 + cur + m * 2304 + (2 * c + s2) * 32);
            #pragma unroll
            for (int n = 0; n < 8; n++) {
                uint32 b0, b1, b2, b3;
                ldsm4(b0, b1, b2, b3, bAddrW + cur + n * 1152 + c * 64);
                #pragma unroll
                for (int m = 0; m < 2; m++) {
                    mma_f16(acc[m][n][0], acc[m][n][1], acc[m][n][2], acc[m][n][3],
                            a[m][0][0], a[m][0][1], a[m][0][2], a[m][0][3], b0, b1);
                    mma_f16(acc[m][n][0], acc[m][n][1], acc[m][n][2], acc[m][n][3],
                            a[m][1][0], a[m][1][1], a[m][1][2], a[m][1][3], b2, b3);
                }
            }
        }
        if (cc < 7) {
            __syncthreads();
            __half* sAn = sA + ((cc + 1) & 1) * (128 * 72);
            #pragma unroll
            for (int i = 0; i < 4; i++)
                *reinterpret_cast<uint4*>(sAn + (lr + i * 32) * 72 + c8) =
                    pack8(ar[i][0], ar[i][1]);
            CP_WAIT0();
            __syncthreads();
        }
    }
    #pragma unroll
    for (int m = 0; m < 2; m++) {
        #pragma unroll
        for (int n = 0; n < 8; n++) {
            const int col = wc + n * 8 + 2 * tig;
            const size_t r0 = (size_t)rowBase + wr + m * 16 + g;
            *(float2*)(&outp[r0 * 128 + col]) =
                make_float2(acc[m][n][0], acc[m][n][1]);
            *(float2*)(&outp[(r0 + 8) * 128 + col]) =
                make_float2(acc[m][n][2], acc[m][n][3]);
        }
    }
}

// ============================================================================
// reduce split-K partials + bias + LayerNorm -> g_xrh (half)  (R12-proven)
// ============================================================================
__global__ __launch_bounds__(128) void reduce_ln(
    const float* __restrict__ bias,
    const float* __restrict__ gamma, const float* __restrict__ beta)
{
    const int row = blockIdx.x;
    const int t = threadIdx.x;
    const size_t o = (size_t)row * 128 + t;
    const size_t STRIDE = (size_t)BB * NP * CC;
    float v = g_cpart[o] + g_cpart[STRIDE + o] + g_cpart[2 * STRIDE + o]
            + g_cpart[3 * STRIDE + o] + bias[t];
    float s = v, s2 = v * v;
    #pragma unroll
    for (int mask = 16; mask > 0; mask >>= 1) {
        s  += __shfl_xor_sync(0xffffffffu, s,  mask);
        s2 += __shfl_xor_sync(0xffffffffu, s2, mask);
    }
    __shared__ float red[8];
    const int w = t >> 5;
    if ((t & 31) == 0) { red[w] = s; red[4 + w] = s2; }
    __syncthreads();
    const float S  = red[0] + red[1] + red[2] + red[3];
    const float S2 = red[4] + red[5] + red[6] + red[7];
    const float mu  = S * (1.0f / 128.0f);
    const float var = S2 * (1.0f / 128.0f) - mu * mu;
    g_xrh[o] = __float2half(
        (v - mu) * rsqrtf(var + LN_EPS) * gamma[t] + beta[t]);
}

// ============================================================================
// gemm core (single-phase, R12-proven): full K=128 resident, 4 mma chunks.
// ============================================================================
template <bool HALF_OUT>
__device__ __forceinline__ void gemm_core(
    const __half* __restrict__ Ah, const __half* __restrict__ Wt,
    void* __restrict__ outv, size_t rowBase, __half* sA, __half* sB)
{
    const int tid = threadIdx.x, lane = tid & 31, wid = tid >> 5;
    const int g = lane >> 2, tig = lane & 3;
    const int laneJ = lane >> 3, laneR = lane & 7;
    const int wr = (wid & 3) * 32;
    const int wc = (wid >> 2) * 64;
    const int lr = tid >> 3;
    const int c16 = (tid & 7) * 16;

    const uint32 sAb = smem_u32(sA), sBb = smem_u32(sB);
    const uint32 aAddr0 = sAb + (uint32)((wr + (laneJ & 1) * 8 + laneR) * 272
                                         + (laneJ >> 1) * 16);
    const uint32 bAddrW = sBb + (uint32)((wc + laneR) * 272 + laneJ * 16);

    #pragma unroll
    for (int i = 0; i < 4; i++) {
        const int r = lr + i * 32;
        const __half* Ap = Ah + (rowBase + r) * 128 + c16;
        *reinterpret_cast<uint4*>(sA + r * 136 + c16)     = ((const uint4*)Ap)[0];
        *reinterpret_cast<uint4*>(sA + r * 136 + c16 + 8) = ((const uint4*)Ap)[1];
        const __half* Wp = Wt + (size_t)r * 128 + c16;
        *reinterpret_cast<uint4*>(sB + r * 136 + c16)     = ((const uint4*)Wp)[0];
        *reinterpret_cast<uint4*>(sB + r * 136 + c16 + 8) = ((const uint4*)Wp)[1];
    }
    __syncthreads();

    float acc[2][8][4];
    #pragma unroll
    for (int m = 0; m < 2; m++)
        #pragma unroll
        for (int n = 0; n < 8; n++)
            #pragma unroll
            for (int q = 0; q < 4; q++) acc[m][n][q] = 0.0f;

    #pragma unroll
    for (int c = 0; c < 4; c++) {
        uint32 a[2][2][4];
        #pragma unroll
        for (int m = 0; m < 2; m++)
            #pragma unroll
            for (int s2 = 0; s2 < 2; s2++)
                ldsm4(a[m][s2][0], a[m][s2][1], a[m][s2][2], a[m][s2][3],
                      aAddr0 + m * 4352 + (2 * c + s2) * 32);
        #pragma unroll
        for (int n = 0; n < 8; n++) {
            uint32 b0, b1, b2, b3;
            ldsm4(b0, b1, b2, b3, bAddrW + n * 2176 + c * 64);
            #pragma unroll
            for (int m = 0; m < 2; m++) {
                mma_f16(acc[m][n][0], acc[m][n][1], acc[m][n][2], acc[m][n][3],
                        a[m][0][0], a[m][0][1], a[m][0][2], a[m][0][3], b0, b1);
                mma_f16(acc[m][n][0], acc[m][n][1], acc[m][n][2], acc[m][n][3],
                        a[m][1][0], a[m][1][1], a[m][1][2], a[m][1][3], b2, b3);
            }
        }
    }
    #pragma unroll
    for (int m = 0; m < 2; m++) {
        #pragma unroll
        for (int n = 0; n < 8; n++) {
            const int col = wc + n * 8 + 2 * tig;
            const size_t r0 = rowBase + wr + m * 16 + g;
            if (HALF_OUT) {
                __half2* o = reinterpret_cast<__half2*>(outv);
                o[(r0 * 128 + col) >> 1] =
                    __floats2half2_rn(acc[m][n][0], acc[m][n][1]);
                o[((r0 + 8) * 128 + col) >> 1] =
                    __floats2half2_rn(acc[m][n][2], acc[m][n][3]);
            } else {
                float* o = reinterpret_cast<float*>(outv);
                *(float2*)(o + r0 * 128 + col) =
                    make_float2(acc[m][n][0], acc[m][n][1]);
                *(float2*)(o + (r0 + 8) * 128 + col) =
                    make_float2(acc[m][n][2], acc[m][n][3]);
            }
        }
    }
}

#define GEMM_SMEM (2 * 128 * 136 * 2)   // 69632 bytes

__global__ __launch_bounds__(256) void gemm_kv()
{
    extern __shared__ __align__(16) __half gs[];
    const __half* Wt = blockIdx.y ? g_wvT : g_wkT;
    __half* out      = blockIdx.y ? g_vh  : g_kh;
    gemm_core<true>(g_xrh, Wt, out, (size_t)blockIdx.x * 128, gs, gs + 128 * 136);
}

__global__ __launch_bounds__(256) void gemm_out(float* __restrict__ out)
{
    extern __shared__ __align__(16) __half gs[];
    gemm_core<false>(g_aoh, g_wpT, out, (size_t)blockIdx.x * 128,
                     gs, gs + 128 * 136);
}

// ============================================================================
// fused flash attention v2: 128 threads / 4 warps, each warp owns 32 query
//   rows (2 m-tiles) -> every K/V fragment load feeds 2 mma, halving the
//   L1/smem read amplification that bound R13's kernel (L1 was 76.5%).
//   In-kernel Q projection, 3-stage cp.async KV pipeline (55.3 KB, 3 CTA/SM),
//   f16-accum S with in-place ex2 (P frags = re-indexed exp'd S frags),
//   f32-accum PV. CTA = 128 queries x one (b,h).
// ============================================================================
#define STAGEB 18432
#define ATTN_SMEM (3 * STAGEB)   // 55296

__device__ __forceinline__ void kv_prefetch4(
    uint32 kDst, uint32 vDst, const __half* Kg, const __half* Vg,
    int chunk, int lr, int c8)
{
    const size_t nb = (size_t)(chunk * 64) * CC;
    #pragma unroll
    for (int i = 0; i < 4; i++) {
        cp16(kDst + i * 2304, Kg + nb + (size_t)(lr + i * 16) * CC + c8);
        cp16(vDst + i * 2304, Vg + nb + (size_t)(lr + i * 16) * CC + c8);
    }
}

__global__ __launch_bounds__(128, 3) void attn_f(const float* __restrict__ x)
{
    extern __shared__ __align__(16) __half as_[];
    const uint32 smb = smem_u32(as_);
    const int tid = threadIdx.x, lane = tid & 31, wid = tid >> 5;  // wid 0..3
    const int g = lane >> 2, tig = lane & 3;
    const int laneJ = lane >> 3, laneR = lane & 7;
    const int b = blockIdx.y >> 1, h = blockIdx.y & 1;
    const int qbase = blockIdx.x * 128;
    const int wr = wid * 32;              // warp's 32 rows; m-tile m at wr+m*16

    const __half* Kg = g_kh + ((size_t)b * NP) * CC + h * DH;
    const __half* Vg = g_vh + ((size_t)b * NP) * CC + h * DH;

    // ---------------- Phase 1: Q = x @ Wq[:, h*64 .. h*64+63] ----------------
    __half* sX = as_;                 // 128 x 136 (34816 B)
    __half* sW = as_ + 128 * 136;     // 64 x 136 (17408 B)  total 52224 <= 55296
    {
        const int lr1 = tid >> 3;             // 0..15
        const int c16 = (tid & 7) * 16;
        #pragma unroll
        for (int i = 0; i < 8; i++) {
            const int r = lr1 + i * 16;
            const float* src = x + ((size_t)b * NN + qbase + r) * 128 + c16;
            float4 f0 = ((const float4*)src)[0];
            float4 f1 = ((const float4*)src)[1];
            float4 f2 = ((const float4*)src)[2];
            float4 f3 = ((const float4*)src)[3];
            *reinterpret_cast<uint4*>(sX + r * 136 + c16)     = pack8(f0, f1);
            *reinterpret_cast<uint4*>(sX + r * 136 + c16 + 8) = pack8(f2, f3);
        }
        const int row = tid >> 1;             // 0..63
        const int cb = (tid & 1) * 64;
        const __half* Wp = g_wqT + (size_t)(h * 64 + row) * 128 + cb;
        #pragma unroll
        for (int j = 0; j < 8; j++)
            *reinterpret_cast<uint4*>(sW + row * 136 + cb + j * 8) =
                ((const uint4*)Wp)[j];
    }
    __syncthreads();

    uint32 qf[2][4][4];
    {
        const uint32 sXb = smem_u32(sX), sWb = smem_u32(sW);
        const uint32 aAddrQ = sXb + (uint32)((wr + (laneJ & 1) * 8 + laneR) * 272
                                             + (laneJ >> 1) * 16);
        const uint32 bAddrQ = sWb + (uint32)(laneR * 272 + laneJ * 16);
        float qa[2][8][4];
        #pragma unroll
        for (int m = 0; m < 2; m++)
            #pragma unroll
            for (int n = 0; n < 8; n++)
                #pragma unroll
                for (int q = 0; q < 4; q++) qa[m][n][q] = 0.0f;
        #pragma unroll
        for (int c = 0; c < 4; c++) {
            uint32 a[2][2][4];
            #pragma unroll
            for (int m = 0; m < 2; m++)
                #pragma unroll
                for (int s2 = 0; s2 < 2; s2++)
                    ldsm4(a[m][s2][0], a[m][s2][1], a[m][s2][2], a[m][s2][3],
                          aAddrQ + m * 4352 + (2 * c + s2) * 32);
            #pragma unroll
            for (int n = 0; n < 8; n++) {
                uint32 b0, b1, b2, b3;
                ldsm4(b0, b1, b2, b3, bAddrQ + n * 2176 + c * 64);
                #pragma unroll
                for (int m = 0; m < 2; m++) {
                    mma_f16(qa[m][n][0], qa[m][n][1], qa[m][n][2], qa[m][n][3],
                            a[m][0][0], a[m][0][1], a[m][0][2], a[m][0][3], b0, b1);
                    mma_f16(qa[m][n][0], qa[m][n][1], qa[m][n][2], qa[m][n][3],
                            a[m][1][0], a[m][1][1], a[m][1][2], a[m][1][3], b2, b3);
                }
            }
        }
        #pragma unroll
        for (int m = 0; m < 2; m++)
            #pragma unroll
            for (int s = 0; s < 4; s++) {
                qf[m][s][0] = packh2(qa[m][2 * s][0] * QSCALE_LOG2,
                                     qa[m][2 * s][1] * QSCALE_LOG2);
                qf[m][s][1] = packh2(qa[m][2 * s][2] * QSCALE_LOG2,
                                     qa[m][2 * s][3] * QSCALE_LOG2);
                qf[m][s][2] = packh2(qa[m][2 * s + 1][0] * QSCALE_LOG2,
                                     qa[m][2 * s + 1][1] * QSCALE_LOG2);
                qf[m][s][3] = packh2(qa[m][2 * s + 1][2] * QSCALE_LOG2,
                                     qa[m][2 * s + 1][3] * QSCALE_LOG2);
            }
    }
    __syncthreads();   // done with sX/sW; smem becomes KV stages

    // ---------------- Phase 2: KV loop, 3-stage pipeline ----------------
    const uint32 kAddr0 = smb + (uint32)(laneR * 144 + laneJ * 16);
    const uint32 vAddr0 = smb + 9216u + (uint32)((laneJ * 8 + laneR) * 144);
    const int lr = tid >> 3;              // 0..15
    const int c8 = (tid & 7) * 8;
    const uint32 kDst = smb + (uint32)(lr * 144 + c8 * 2);
    const uint32 vDst = smb + 9216u + (uint32)(lr * 144 + c8 * 2);

    float O[2][8][4];
    #pragma unroll
    for (int m = 0; m < 2; m++)
        #pragma unroll
        for (int n = 0; n < 8; n++)
            #pragma unroll
            for (int q = 0; q < 4; q++) O[m][n][q] = 0.0f;
    float ls[2][2] = {{0.0f, 0.0f}, {0.0f, 0.0f}};

    #pragma unroll
    for (int p = 0; p < 2; p++) {
        kv_prefetch4(kDst + p * STAGEB, vDst + p * STAGEB, Kg, Vg, p, lr, c8);
        CP_COMMIT();
    }

    int scur = 0;
    int spre = 2;
    for (int kc = 0; kc < 16; kc++) {
        CP_WAIT1();
        __syncthreads();

        {
            const int nx = kc + 2;
            if (nx < 16) {
                const uint32 st = (uint32)(spre * STAGEB);
                kv_prefetch4(kDst + st, vDst + st, Kg, Vg, nx, lr, c8);
            }
            CP_COMMIT();
        }

        const uint32 bo = (uint32)(scur * STAGEB);

        // S = Q K^T (log2 domain), fp16 accumulators; K frags shared by both m
        uint32 Sd[2][8][2];
        #pragma unroll
        for (int m = 0; m < 2; m++)
            #pragma unroll
            for (int n = 0; n < 8; n++) { Sd[m][n][0] = 0u; Sd[m][n][1] = 0u; }
        #pragma unroll
        for (int c = 0; c < 2; c++) {
            #pragma unroll
            for (int n = 0; n < 8; n++) {
                uint32 b0, b1, b2, b3;
                ldsm4(b0, b1, b2, b3, kAddr0 + bo + n * 1152 + c * 64);
                #pragma unroll
                for (int m = 0; m < 2; m++) {
                    mma_f16h(Sd[m][n][0], Sd[m][n][1],
                             qf[m][2 * c][0], qf[m][2 * c][1],
                             qf[m][2 * c][2], qf[m][2 * c][3], b0, b1);
                    mma_f16h(Sd[m][n][0], Sd[m][n][1],
                             qf[m][2 * c + 1][0], qf[m][2 * c + 1][1],
                             qf[m][2 * c + 1][2], qf[m][2 * c + 1][3], b2, b3);
                }
            }
        }

        // P = 2^S in place; accumulate quantized row sums
        #pragma unroll
        for (int m = 0; m < 2; m++)
            #pragma unroll
            for (int n = 0; n < 8; n++) {
                Sd[m][n][0] = ex2acc(Sd[m][n][0], ls[m][0]);
                Sd[m][n][1] = ex2acc(Sd[m][n][1], ls[m][1]);
            }

        // O += P V  (V frags shared by both m; A-frag for k-step t of m is
        //   {Sd[m][2t][0], Sd[m][2t][1], Sd[m][2t+1][0], Sd[m][2t+1][1]})
        #pragma unroll
        for (int c = 0; c < 2; c++) {
            #pragma unroll
            for (int n = 0; n < 8; n++) {
                uint32 b0, b1, b2, b3;
                ldsm4t(b0, b1, b2, b3, vAddr0 + bo + c * 4608 + n * 16);
                #pragma unroll
                for (int m = 0; m < 2; m++) {
                    mma_f16(O[m][n][0], O[m][n][1], O[m][n][2], O[m][n][3],
                            Sd[m][4 * c][0], Sd[m][4 * c][1],
                            Sd[m][4 * c + 1][0], Sd[m][4 * c + 1][1], b0, b1);
                    mma_f16(O[m][n][0], O[m][n][1], O[m][n][2], O[m][n][3],
                            Sd[m][4 * c + 2][0], Sd[m][4 * c + 2][1],
                            Sd[m][4 * c + 3][0], Sd[m][4 * c + 3][1], b2, b3);
                }
            }
        }

        scur = (scur == 2) ? 0 : scur + 1;
        spre = (spre == 2) ? 0 : spre + 1;
    }

    // quad-reduce sums, normalize, store half
    #pragma unroll
    for (int m = 0; m < 2; m++) {
        float l0 = ls[m][0], l1 = ls[m][1];
        l0 += __shfl_xor_sync(0xffffffffu, l0, 1);
        l0 += __shfl_xor_sync(0xffffffffu, l0, 2);
        l1 += __shfl_xor_sync(0xffffffffu, l1, 1);
        l1 += __shfl_xor_sync(0xffffffffu, l1, 2);
        const float inv0 = 1.0f / l0;
        const float inv1 = 1.0f / l1;
        __half2* ao2 = reinterpret_cast<__half2*>(g_aoh);
        const size_t org  = ((size_t)b * NN + qbase + wr + m * 16 + g) * 64
                          + h * 32;
        const size_t org8 = org + 8 * 64;
        #pragma unroll
        for (int n = 0; n < 8; n++) {
            ao2[org  + 4 * n + tig] =
                __floats2half2_rn(O[m][n][0] * inv0, O[m][n][1] * inv0);
            ao2[org8 + 4 * n + tig] =
                __floats2half2_rn(O[m][n][2] * inv1, O[m][n][3] * inv1);
        }
    }
}

// ============================================================================
// launch
// ============================================================================
extern "C" void kernel_launch(void* const* d_in, const int* in_sizes, int n_in,
                              void* d_out, int out_size)
{
    const float* x     = (const float*)d_in[0];
    const float* Wq    = (const float*)d_in[1];
    const float* Wk    = (const float*)d_in[2];
    const float* Wv    = (const float*)d_in[3];
    const float* Wproj = (const float*)d_in[4];
    const float* srk   = (const float*)d_in[5];
    const float* srb   = (const float*)d_in[6];
    const float* gamma = (const float*)d_in[7];
    const float* beta  = (const float*)d_in[8];
    float* out = (float*)d_out;

    const int convSmem = 4 * 128 * 72 * 2;    // 73728
    cudaFuncSetAttribute(conv_h,
        cudaFuncAttributeMaxDynamicSharedMemorySize, convSmem);
    cudaFuncSetAttribute(gemm_kv,
        cudaFuncAttributeMaxDynamicSharedMemorySize, GEMM_SMEM);
    cudaFuncSetAttribute(gemm_out,
        cudaFuncAttributeMaxDynamicSharedMemorySize, GEMM_SMEM);
    cudaFuncSetAttribute(attn_f,
        cudaFuncAttributeMaxDynamicSharedMemorySize, ATTN_SMEM);

    // 0) weight conversions
    prep_w<<<1088, 256>>>(Wq, Wk, Wv, Wproj, srk);
    // 1) SR conv (patch GEMM), split-K x4, pipelined
    conv_h<<<dim3(32, 4), 256, convSmem>>>(x);
    // 2) reduce + bias + LayerNorm -> g_xrh (half)
    reduce_ln<<<BB * NP, 128>>>(srb, gamma, beta);
    // 3) K + V projections in one launch
    gemm_kv<<<dim3(32, 2), 256, GEMM_SMEM>>>();
    // 4+5) fused Q projection + attention v2 (4 warps, 2 m-tiles/warp)
    attn_f<<<dim3(NN / 128, BB * 2), 128, ATTN_SMEM>>>(x);
    // 6) output projection -> d_out (f32)
    gemm_out<<<512, 256, GEMM_SMEM>>>(out);
}